// round 10
// baseline (speedup 1.0000x reference)
#include <cuda_runtime.h>

// CombPool2d: out = (w_avg^2)*avg_pool2x2(x) + (w_max^2)*max_pool2x2(x)
// x: (16,192,224,224) f32, w_avg/w_max: (1,192,1,1), out: (16,192,112,112)
//
// HBM-bound streaming kernel (~771 MB). R2/R4/R5 all converge at ~7.1TB/s
// (~89% DRAM cycles). R9: raise bytes-in-flight per SM. Each thread:
//   4x LDG.256 (input rows 2oh..2oh+3, 128B, guaranteed front-batched since
//   each v8 load is one indivisible SASS instruction)
//   -> 8 output pixels across 2 output rows -> 2x STG.128.

#define IH 224
#define IW 224
#define OH 112
#define OW 112
#define C_CH 192
#define EW (IW / 8)          // 28 8-float chunks per input row
#define OH2 (OH / 2)         // 56 output-row pairs

__global__ void __launch_bounds__(256, 5)
combpool2d_kernel(const float* __restrict__ x,
                  const float* __restrict__ w_avg,
                  const float* __restrict__ w_max,
                  float* __restrict__ out,
                  int total)
{
    int i = blockIdx.x * blockDim.x + threadIdx.x;
    if (i >= total) return;

    // i -> (bc, oh2, ew) with compile-time-constant divisors
    int ew  = i % EW;
    int t   = i / EW;
    int oh2 = t % OH2;         // output-row pair index
    int bc  = t / OH2;         // fused batch*channel, 0..3071
    int c   = bc % C_CH;

    float wa = __ldg(w_avg + c);
    float wm = __ldg(w_max + c);
    wa = wa * wa * 0.25f;      // fold 1/(K*K) into the avg coefficient
    wm = wm * wm;

    const float* r0 = x + (size_t)bc * (IH * IW) + (size_t)(4 * oh2) * IW + ew * 8;
    const float* r1 = r0 + IW;
    const float* r2 = r1 + IW;
    const float* r3 = r2 + IW;

    // Four front-batched 256-bit loads (128B/thread in flight).
    float a0,a1,a2,a3,a4,a5,a6,a7;
    float b0,b1,b2,b3,b4,b5,b6,b7;
    float c0,c1,c2,c3,c4,c5,c6,c7;
    float d0,d1,d2,d3,d4,d5,d6,d7;
    asm volatile("ld.global.nc.v8.f32 {%0,%1,%2,%3,%4,%5,%6,%7}, [%8];"
                 : "=f"(a0),"=f"(a1),"=f"(a2),"=f"(a3),
                   "=f"(a4),"=f"(a5),"=f"(a6),"=f"(a7) : "l"(r0));
    asm volatile("ld.global.nc.v8.f32 {%0,%1,%2,%3,%4,%5,%6,%7}, [%8];"
                 : "=f"(b0),"=f"(b1),"=f"(b2),"=f"(b3),
                   "=f"(b4),"=f"(b5),"=f"(b6),"=f"(b7) : "l"(r1));
    asm volatile("ld.global.nc.v8.f32 {%0,%1,%2,%3,%4,%5,%6,%7}, [%8];"
                 : "=f"(c0),"=f"(c1),"=f"(c2),"=f"(c3),
                   "=f"(c4),"=f"(c5),"=f"(c6),"=f"(c7) : "l"(r2));
    asm volatile("ld.global.nc.v8.f32 {%0,%1,%2,%3,%4,%5,%6,%7}, [%8];"
                 : "=f"(d0),"=f"(d1),"=f"(d2),"=f"(d3),
                   "=f"(d4),"=f"(d5),"=f"(d6),"=f"(d7) : "l"(r3));

    float4 o0, o1;
    o0.x = wa * (a0 + a1 + b0 + b1) + wm * fmaxf(fmaxf(a0, a1), fmaxf(b0, b1));
    o0.y = wa * (a2 + a3 + b2 + b3) + wm * fmaxf(fmaxf(a2, a3), fmaxf(b2, b3));
    o0.z = wa * (a4 + a5 + b4 + b5) + wm * fmaxf(fmaxf(a4, a5), fmaxf(b4, b5));
    o0.w = wa * (a6 + a7 + b6 + b7) + wm * fmaxf(fmaxf(a6, a7), fmaxf(b6, b7));

    o1.x = wa * (c0 + c1 + d0 + d1) + wm * fmaxf(fmaxf(c0, c1), fmaxf(d0, d1));
    o1.y = wa * (c2 + c3 + d2 + d3) + wm * fmaxf(fmaxf(c2, c3), fmaxf(d2, d3));
    o1.z = wa * (c4 + c5 + d4 + d5) + wm * fmaxf(fmaxf(c4, c5), fmaxf(d4, d5));
    o1.w = wa * (c6 + c7 + d6 + d7) + wm * fmaxf(fmaxf(c6, c7), fmaxf(d6, d7));

    float* obase = out + (size_t)bc * (OH * OW) + (size_t)(2 * oh2) * OW + ew * 4;
    *reinterpret_cast<float4*>(obase)      = o0;
    *reinterpret_cast<float4*>(obase + OW) = o1;
}

extern "C" void kernel_launch(void* const* d_in, const int* in_sizes, int n_in,
                              void* d_out, int out_size)
{
    const float* x     = (const float*)d_in[0];
    const float* w_avg = (const float*)d_in[1];
    const float* w_max = (const float*)d_in[2];
    float* out = (float*)d_out;

    int total = out_size / 8;                     // 4,816,896 threads
    int threads = 256;
    int blocks = (total + threads - 1) / threads;
    combpool2d_kernel<<<blocks, threads>>>(x, w_avg, w_max, out, total);
}